// round 1
// baseline (speedup 1.0000x reference)
#include <cuda_runtime.h>
#include <math_constants.h>

#define NN_  8192
#define DIN_ 1024
#define DD_  256
#define KT_  30

// ---------------- scratch (static device globals: allocation-free) ----------
__device__ float g_P[(size_t)NN_ * NN_];     // attn logits [N,N]  (256 MB)
__device__ float g_h1[NN_ * DD_];
__device__ float g_h [NN_ * DD_];
__device__ float g_eh[NN_ * DD_];
__device__ float g_et[NN_ * DD_];
__device__ float g_U [NN_ * DD_];
__device__ float g_V [NN_ * DD_];
__device__ float g_E1[NN_ * DD_];
__device__ int   g_tI[NN_ * KT_];
__device__ float g_tP[NN_ * KT_];
__device__ float g_att[NN_];
__device__ float g_red[2];
__device__ float g_part[32 * DD_];

// ---------------- generic tiled SGEMM: C = act(alpha*A@B(+/-T) + bias) + addend
// BM=BN=128, BK=8, 256 threads, 8x8 microtile. Requires M%128==0, N%128==0, K%8==0.
template<bool TRANSB, bool DORELU>
__global__ void __launch_bounds__(256) sgemm_kernel(
    const float* __restrict__ A, const float* __restrict__ B,
    const float* __restrict__ bias, const float* __restrict__ addend,
    float* __restrict__ C, int M, int Nc, int Kd, float alpha)
{
    __shared__ float As[8][128];
    __shared__ float Bs[8][128];
    const int tid  = threadIdx.x;
    const int bx   = blockIdx.x * 128;
    const int by   = blockIdx.y * 128;
    const int row0 = (tid >> 4) * 8;
    const int col0 = (tid & 15) * 8;
    const int lRow = tid >> 1;          // 0..127
    const int lK   = (tid & 1) * 4;     // 0 or 4

    float acc[8][8];
    #pragma unroll
    for (int i = 0; i < 8; i++)
        #pragma unroll
        for (int j = 0; j < 8; j++) acc[i][j] = 0.f;

    for (int k0 = 0; k0 < Kd; k0 += 8) {
        float4 a = *reinterpret_cast<const float4*>(A + (size_t)(by + lRow) * Kd + k0 + lK);
        As[lK+0][lRow] = a.x; As[lK+1][lRow] = a.y; As[lK+2][lRow] = a.z; As[lK+3][lRow] = a.w;
        if (TRANSB) {
            float4 b = *reinterpret_cast<const float4*>(B + (size_t)(bx + lRow) * Kd + k0 + lK);
            Bs[lK+0][lRow] = b.x; Bs[lK+1][lRow] = b.y; Bs[lK+2][lRow] = b.z; Bs[lK+3][lRow] = b.w;
        } else {
            const int bK = tid >> 5;
            const int bC = (tid & 31) * 4;
            float4 b = *reinterpret_cast<const float4*>(B + (size_t)(k0 + bK) * Nc + bx + bC);
            *reinterpret_cast<float4*>(&Bs[bK][bC]) = b;
        }
        __syncthreads();
        #pragma unroll
        for (int kk = 0; kk < 8; kk++) {
            float4 a0 = *reinterpret_cast<const float4*>(&As[kk][row0]);
            float4 a1 = *reinterpret_cast<const float4*>(&As[kk][row0 + 4]);
            float4 b0 = *reinterpret_cast<const float4*>(&Bs[kk][col0]);
            float4 b1 = *reinterpret_cast<const float4*>(&Bs[kk][col0 + 4]);
            float ra[8] = {a0.x,a0.y,a0.z,a0.w,a1.x,a1.y,a1.z,a1.w};
            float rb[8] = {b0.x,b0.y,b0.z,b0.w,b1.x,b1.y,b1.z,b1.w};
            #pragma unroll
            for (int i = 0; i < 8; i++)
                #pragma unroll
                for (int j = 0; j < 8; j++)
                    acc[i][j] += ra[i] * rb[j];
        }
        __syncthreads();
    }

    #pragma unroll
    for (int i = 0; i < 8; i++) {
        const size_t r = (size_t)(by + row0 + i);
        #pragma unroll
        for (int j = 0; j < 8; j++) {
            const int c = bx + col0 + j;
            float v = acc[i][j] * alpha;
            if (bias)   v += bias[c];
            if (DORELU) v  = fmaxf(v, 0.f);
            if (addend) v += addend[r * Nc + c];
            C[r * Nc + c] = v;
        }
    }
}

// ---------------- per-row top-30 (iterative argmax, jax tie-break: lower index)
__global__ void __launch_bounds__(256) topk_kernel(const float* __restrict__ P,
                                                   int* __restrict__ tI,
                                                   float* __restrict__ tP)
{
    const int row  = blockIdx.x;
    const int tid  = threadIdx.x;
    const int lane = tid & 31, w = tid >> 5;
    const float* p = P + (size_t)row * NN_;

    float v[32];
    #pragma unroll
    for (int j = 0; j < 32; j++) v[j] = p[tid + j * 256];

    __shared__ float sV[8];
    __shared__ int   sI[9];
    __shared__ float selV[KT_];
    __shared__ int   selI[KT_];

    for (int it = 0; it < KT_; it++) {
        // local argmax over 32 register elements (strict > keeps lowest j => lowest index)
        float bv = v[0]; int bj = 0;
        #pragma unroll
        for (int j = 1; j < 32; j++) if (v[j] > bv) { bv = v[j]; bj = j; }
        int bi = tid + bj * 256;
        // warp argmax
        #pragma unroll
        for (int off = 16; off; off >>= 1) {
            float ov = __shfl_xor_sync(0xffffffffu, bv, off);
            int   oi = __shfl_xor_sync(0xffffffffu, bi, off);
            if (ov > bv || (ov == bv && oi < bi)) { bv = ov; bi = oi; }
        }
        if (lane == 0) { sV[w] = bv; sI[w] = bi; }
        __syncthreads();
        if (tid == 0) {
            float Bv = sV[0]; int Bi = sI[0];
            #pragma unroll
            for (int q = 1; q < 8; q++)
                if (sV[q] > Bv || (sV[q] == Bv && sI[q] < Bi)) { Bv = sV[q]; Bi = sI[q]; }
            selV[it] = Bv; selI[it] = Bi; sI[8] = Bi;
        }
        __syncthreads();
        const int win = sI[8];
        if ((win & 255) == tid) {
            const int jj = win >> 8;
            #pragma unroll
            for (int j = 0; j < 32; j++) if (j == jj) v[j] = -CUDART_INF_F;
        }
    }
    __syncthreads();
    if (tid < 32) {
        float ev = (tid < KT_) ? expf(selV[tid] - selV[0]) : 0.f;
        float s = ev;
        #pragma unroll
        for (int off = 16; off; off >>= 1) s += __shfl_xor_sync(0xffffffffu, s, off);
        if (tid < KT_) {
            tP[row * KT_ + tid] = ev / s;
            tI[row * KT_ + tid] = selI[tid];
        }
    }
}

// ---------------- fused neighbor aggregation per row ------------------------
// gate = tanh((2-p)*e_h + p*Nb); ka = softmax(sum(Nb)*sum(gate)); eNh = ka @ Nb
// Outputs U = e_h + eNh, V = e_h * eNh
__global__ void __launch_bounds__(256) neighbor_kernel(
    const float* __restrict__ eH, const float* __restrict__ eT,
    const int* __restrict__ tI, const float* __restrict__ tP,
    float* __restrict__ U, float* __restrict__ V)
{
    const int row  = blockIdx.x;
    const int d    = threadIdx.x;
    const int lane = d & 31, w = d >> 5;

    __shared__ float sNb[KT_][DD_];
    __shared__ float sEh[DD_];
    __shared__ float sP[KT_];
    __shared__ int   sIdx[KT_];
    __shared__ float sW[KT_];
    __shared__ float sPr[KT_];

    const float eh = eH[(size_t)row * DD_ + d];
    sEh[d] = eh;
    if (d < KT_) { sP[d] = tP[row * KT_ + d]; sIdx[d] = tI[row * KT_ + d]; }
    __syncthreads();

    #pragma unroll
    for (int k = 0; k < KT_; k++) sNb[k][d] = eT[(size_t)sIdx[k] * DD_ + d];
    __syncthreads();

    for (int k = w; k < KT_; k += 8) {
        const float pk = sP[k], ck = 2.f - pk;
        float snb = 0.f, sg = 0.f;
        #pragma unroll
        for (int q = 0; q < 8; q++) {
            const int dd = lane + q * 32;
            const float nb = sNb[k][dd];
            snb += nb;
            sg  += tanhf(ck * sEh[dd] + pk * nb);
        }
        #pragma unroll
        for (int off = 16; off; off >>= 1) {
            snb += __shfl_xor_sync(0xffffffffu, snb, off);
            sg  += __shfl_xor_sync(0xffffffffu, sg,  off);
        }
        if (lane == 0) sW[k] = snb * sg;
    }
    __syncthreads();

    if (d < 32) {
        float val = (d < KT_) ? sW[d] : -CUDART_INF_F;
        float m = val;
        #pragma unroll
        for (int off = 16; off; off >>= 1) m = fmaxf(m, __shfl_xor_sync(0xffffffffu, m, off));
        float ev = (d < KT_) ? expf(val - m) : 0.f;
        float s = ev;
        #pragma unroll
        for (int off = 16; off; off >>= 1) s += __shfl_xor_sync(0xffffffffu, s, off);
        if (d < KT_) sPr[d] = ev / s;
    }
    __syncthreads();

    float acc = 0.f;
    #pragma unroll
    for (int k = 0; k < KT_; k++) acc += sPr[k] * sNb[k][d];
    U[(size_t)row * DD_ + d] = eh + acc;
    V[(size_t)row * DD_ + d] = eh * acc;
}

// ---------------- attention head: att = leaky(e@W1+b1) @ W2 + b2 ------------
__global__ void __launch_bounds__(128) att_kernel(
    const float* __restrict__ E, const float* __restrict__ W1,
    const float* __restrict__ b1, const float* __restrict__ W2,
    const float* __restrict__ b2, float* __restrict__ att)
{
    const int r0 = blockIdx.x * 16;
    const int j  = threadIdx.x;
    __shared__ float sE[16][DD_];
    for (int t = j; t < 16 * DD_; t += 128)
        sE[t >> 8][t & 255] = E[(size_t)(r0 + (t >> 8)) * DD_ + (t & 255)];
    __syncthreads();

    float acc[16];
    #pragma unroll
    for (int r = 0; r < 16; r++) acc[r] = 0.f;
    for (int dd = 0; dd < DD_; dd++) {
        const float wv = W1[dd * 128 + j];
        #pragma unroll
        for (int r = 0; r < 16; r++) acc[r] += sE[r][dd] * wv;
    }
    const float bb = b1[j], w2 = W2[j];
    __shared__ float sRed[16][4];
    const int lane = j & 31, w = j >> 5;
    #pragma unroll
    for (int r = 0; r < 16; r++) {
        float val = acc[r] + bb;
        val = (val > 0.f) ? val : 0.01f * val;
        val *= w2;
        #pragma unroll
        for (int off = 16; off; off >>= 1) val += __shfl_xor_sync(0xffffffffu, val, off);
        if (lane == 0) sRed[r][w] = val;
    }
    __syncthreads();
    if (j < 16) att[r0 + j] = sRed[j][0] + sRed[j][1] + sRed[j][2] + sRed[j][3] + b2[0];
}

// ---------------- softmax-over-nodes reduction (max, sumexp) ----------------
__global__ void __launch_bounds__(1024) smred_kernel(const float* __restrict__ att,
                                                     float* __restrict__ red)
{
    const int tid = threadIdx.x;
    __shared__ float s[32];
    float m = -CUDART_INF_F;
    for (int i = tid; i < NN_; i += 1024) m = fmaxf(m, att[i]);
    #pragma unroll
    for (int off = 16; off; off >>= 1) m = fmaxf(m, __shfl_xor_sync(0xffffffffu, m, off));
    if ((tid & 31) == 0) s[tid >> 5] = m;
    __syncthreads();
    if (tid < 32) {
        float mm = s[tid];
        #pragma unroll
        for (int off = 16; off; off >>= 1) mm = fmaxf(mm, __shfl_xor_sync(0xffffffffu, mm, off));
        if (tid == 0) s[0] = mm;
    }
    __syncthreads();
    const float M = s[0];
    __syncthreads();
    float z = 0.f;
    for (int i = tid; i < NN_; i += 1024) z += expf(att[i] - M);
    #pragma unroll
    for (int off = 16; off; off >>= 1) z += __shfl_xor_sync(0xffffffffu, z, off);
    if ((tid & 31) == 0) s[tid >> 5] = z;
    __syncthreads();
    if (tid < 32) {
        float zz = s[tid];
        #pragma unroll
        for (int off = 16; off; off >>= 1) zz += __shfl_xor_sync(0xffffffffu, zz, off);
        if (tid == 0) { red[0] = M; red[1] = zz; }
    }
}

// ---------------- e_g = sum_i softmax(att)_i * e_i  (two-stage, deterministic)
__global__ void __launch_bounds__(256) egpart_kernel(const float* __restrict__ att,
    const float* __restrict__ E, const float* __restrict__ red, float* __restrict__ part)
{
    const int b = blockIdx.x;     // 32 blocks x 256 rows
    const int d = threadIdx.x;
    __shared__ float wsh[256];
    wsh[d] = expf(att[b * 256 + d] - red[0]);
    __syncthreads();
    float acc = 0.f;
    const float* Eb = E + (size_t)b * 256 * DD_;
    for (int i = 0; i < 256; i++) acc += wsh[i] * Eb[(size_t)i * DD_ + d];
    part[b * DD_ + d] = acc;
}

__global__ void __launch_bounds__(256) egfin_kernel(const float* __restrict__ part,
    const float* __restrict__ red, float* __restrict__ eg)
{
    const int d = threadIdx.x;
    float s = 0.f;
    #pragma unroll
    for (int b = 0; b < 32; b++) s += part[b * DD_ + d];
    eg[d] = s / red[1];
}

// ---------------- launcher ---------------------------------------------------
extern "C" void kernel_launch(void* const* d_in, const int* in_sizes, int n_in,
                              void* d_out, int out_size)
{
    const float* x    = (const float*)d_in[0];
    const float* Wfc1 = (const float*)d_in[1];
    const float* bfc1 = (const float*)d_in[2];
    const float* Wfc2 = (const float*)d_in[3];
    const float* bfc2 = (const float*)d_in[4];
    const float* Whd  = (const float*)d_in[5];
    const float* bhd  = (const float*)d_in[6];
    const float* Wtl  = (const float*)d_in[7];
    const float* btl  = (const float*)d_in[8];
    const float* Wl1  = (const float*)d_in[9];
    const float* bl1  = (const float*)d_in[10];
    const float* Wl2  = (const float*)d_in[11];
    const float* bl2  = (const float*)d_in[12];
    const float* Wa1  = (const float*)d_in[13];
    const float* ba1  = (const float*)d_in[14];
    const float* Wa2  = (const float*)d_in[15];
    const float* ba2  = (const float*)d_in[16];

    float *P, *h1, *h, *eh, *et, *U, *V, *E1, *att, *red, *part, *tP;
    int* tI;
    cudaGetSymbolAddress((void**)&P,    g_P);
    cudaGetSymbolAddress((void**)&h1,   g_h1);
    cudaGetSymbolAddress((void**)&h,    g_h);
    cudaGetSymbolAddress((void**)&eh,   g_eh);
    cudaGetSymbolAddress((void**)&et,   g_et);
    cudaGetSymbolAddress((void**)&U,    g_U);
    cudaGetSymbolAddress((void**)&V,    g_V);
    cudaGetSymbolAddress((void**)&E1,   g_E1);
    cudaGetSymbolAddress((void**)&att,  g_att);
    cudaGetSymbolAddress((void**)&red,  g_red);
    cudaGetSymbolAddress((void**)&part, g_part);
    cudaGetSymbolAddress((void**)&tI,   g_tI);
    cudaGetSymbolAddress((void**)&tP,   g_tP);

    float* out = (float*)d_out;
    const size_t ND = (size_t)NN_ * DD_;
    float* e_out;
    float* eg_out;
    if ((size_t)out_size >= ND + DD_)      { e_out = out; eg_out = out + ND; }
    else if ((size_t)out_size >= ND)       { e_out = out; eg_out = nullptr;  }
    else                                   { e_out = h1;  eg_out = out;      }

    const float SCALE = 0.0625f;  // 256^-0.5
    const dim3 gSmall(DD_ / 128, NN_ / 128);   // (2, 64)
    const dim3 gAttn (NN_ / 128, NN_ / 128);   // (64, 64)

    // MLP trunk
    sgemm_kernel<false, true ><<<gSmall, 256>>>(x,  Wfc1, bfc1, nullptr, h1, NN_, DD_, DIN_, 1.f);
    sgemm_kernel<false, true ><<<gSmall, 256>>>(h1, Wfc2, bfc2, nullptr, h,  NN_, DD_, DD_,  1.f);
    sgemm_kernel<false, false><<<gSmall, 256>>>(h,  Whd,  bhd,  nullptr, eh, NN_, DD_, DD_,  1.f);
    sgemm_kernel<false, false><<<gSmall, 256>>>(h,  Wtl,  btl,  nullptr, et, NN_, DD_, DD_,  1.f);

    // pairwise logits (NT) + top-k + neighbor aggregation
    sgemm_kernel<true,  false><<<gAttn, 256>>>(eh, et, nullptr, nullptr, P, NN_, NN_, DD_, SCALE);
    topk_kernel    <<<NN_, 256>>>(P, tI, tP);
    neighbor_kernel<<<NN_, 256>>>(eh, et, tI, tP, U, V);

    // e = relu(U@Wl1+b) + relu(V@Wl2+b)
    sgemm_kernel<false, true ><<<gSmall, 256>>>(U, Wl1, bl1, nullptr, E1,    NN_, DD_, DD_, 1.f);
    sgemm_kernel<false, true ><<<gSmall, 256>>>(V, Wl2, bl2, E1,      e_out, NN_, DD_, DD_, 1.f);

    if (eg_out) {
        att_kernel   <<<NN_ / 16, 128>>>(e_out, Wa1, ba1, Wa2, ba2, att);
        smred_kernel <<<1, 1024>>>(att, red);
        egpart_kernel<<<32, 256>>>(att, e_out, red, part);
        egfin_kernel <<<1, 256>>>(part, red, eg_out);
    }
}

// round 3
// speedup vs baseline: 1.4959x; 1.4959x over previous
#include <cuda_runtime.h>
#include <cuda_bf16.h>
#include <math_constants.h>
#include <cstdint>

#define NN_  8192
#define DIN_ 1024
#define DD_  256
#define KT_  30
#define KSPLIT_ 768   // bf16 hi/lo split: [hi | lo | hi] x [hi | hi | lo]

// ---------------- scratch (static device globals: allocation-free) ----------
__device__ float g_P[(size_t)NN_ * NN_];     // attn logits [N,N]  (256 MB)
__device__ float g_h1[NN_ * DD_];
__device__ float g_h [NN_ * DD_];
__device__ float g_eh[NN_ * DD_];
__device__ float g_et[NN_ * DD_];
__device__ float g_U [NN_ * DD_];
__device__ float g_V [NN_ * DD_];
__device__ float g_E1[NN_ * DD_];
__device__ __nv_bfloat16 g_Abf[(size_t)NN_ * KSPLIT_];   // 12 MB
__device__ __nv_bfloat16 g_Bbf[(size_t)NN_ * KSPLIT_];   // 12 MB
__device__ int   g_tI[NN_ * KT_];
__device__ float g_tP[NN_ * KT_];
__device__ float g_att[NN_];
__device__ float g_red[2];
__device__ float g_part[32 * DD_];

// =================== warp-MMA helpers (sm_80+, compute_103-safe) ============
__device__ __forceinline__ uint32_t smem_u32(const void* p) {
    uint32_t a;
    asm("{ .reg .u64 t; cvta.to.shared.u64 t, %1; cvt.u32.u64 %0, t; }" : "=r"(a) : "l"(p));
    return a;
}
#define SW128(off) ((off) ^ (((off) >> 3) & 0x70))
#define CP16(dst, src)    asm volatile("cp.async.cg.shared.global [%0], [%1], 16;" :: "r"(dst), "l"(src) : "memory")
#define CP_COMMIT()       asm volatile("cp.async.commit_group;" ::: "memory")

__device__ __forceinline__ void ldsm4(uint32_t* r, uint32_t addr) {
    asm volatile("ldmatrix.sync.aligned.m8n8.x4.shared.b16 {%0,%1,%2,%3}, [%4];"
        : "=r"(r[0]), "=r"(r[1]), "=r"(r[2]), "=r"(r[3]) : "r"(addr));
}
__device__ __forceinline__ void mma16816(float* d, const uint32_t* a, const uint32_t* b) {
    asm volatile("mma.sync.aligned.m16n8k16.row.col.f32.bf16.bf16.f32 "
        "{%0,%1,%2,%3}, {%4,%5,%6,%7}, {%8,%9}, {%0,%1,%2,%3};"
        : "+f"(d[0]), "+f"(d[1]), "+f"(d[2]), "+f"(d[3])
        : "r"(a[0]), "r"(a[1]), "r"(a[2]), "r"(a[3]), "r"(b[0]), "r"(b[1]));
}

// ---------------- bf16 hi/lo split of e_h (scaled) and e_t -------------------
__global__ void __launch_bounds__(256) split_kernel(
    const float* __restrict__ eh, const float* __restrict__ et,
    __nv_bfloat16* __restrict__ A, __nv_bfloat16* __restrict__ B)
{
    const int r = blockIdx.x;
    const int c = threadIdx.x;
    const size_t idx = (size_t)r * DD_ + c;
    float xa = eh[idx] * 0.0625f;            // SCALE = 256^-0.5 (exact pow2)
    __nv_bfloat16 ha = __float2bfloat16(xa);
    __nv_bfloat16 la = __float2bfloat16(xa - __bfloat162float(ha));
    A[(size_t)r * KSPLIT_ + c]        = ha;
    A[(size_t)r * KSPLIT_ + 256 + c]  = la;
    A[(size_t)r * KSPLIT_ + 512 + c]  = ha;
    float xb = et[idx];
    __nv_bfloat16 hb = __float2bfloat16(xb);
    __nv_bfloat16 lb = __float2bfloat16(xb - __bfloat162float(hb));
    B[(size_t)r * KSPLIT_ + c]        = hb;
    B[(size_t)r * KSPLIT_ + 256 + c]  = hb;
    B[(size_t)r * KSPLIT_ + 512 + c]  = lb;
}

// ---------------- warp-MMA attn GEMM: P = A' @ B'^T --------------------------
// BM=BN=128, BK=64 bf16. 8 warps (4m x 2n), warp tile 32x64.
// smem per stage: A 16KB + B 16KB; 2 stages = 64KB dynamic smem.
#define ATT_STG 32768
#define ATT_BOFF 16384
#define ATT_NCHUNK 12

__device__ __forceinline__ void attn_fill(uint32_t sbase, int kc, int bm, int bn,
    const __nv_bfloat16* __restrict__ Ag, const __nv_bfloat16* __restrict__ Bg, int tid)
{
    #pragma unroll
    for (int i = 0; i < 4; i++) {               // A: 128 rows x 128B
        int q = tid + i * 256;                  // 0..1023
        int row = q >> 3, c = q & 7;
        const __nv_bfloat16* src = Ag + (size_t)(bm * 128 + row) * KSPLIT_ + kc * 64 + c * 8;
        CP16(sbase + SW128((uint32_t)(row * 128 + c * 16)), src);
    }
    #pragma unroll
    for (int i = 0; i < 4; i++) {               // B: 128 rows x 128B
        int q = tid + i * 256;
        int row = q >> 3, c = q & 7;
        const __nv_bfloat16* src = Bg + (size_t)(bn * 128 + row) * KSPLIT_ + kc * 64 + c * 8;
        CP16(sbase + ATT_BOFF + SW128((uint32_t)(row * 128 + c * 16)), src);
    }
}

__global__ void __launch_bounds__(256, 2) attn_mma_kernel(
    const __nv_bfloat16* __restrict__ Ag, const __nv_bfloat16* __restrict__ Bg,
    float* __restrict__ P)
{
    extern __shared__ char smem[];
    const uint32_t sb = smem_u32(smem);
    const int tid  = threadIdx.x;
    const int wid  = tid >> 5;
    const int lane = tid & 31;
    const int bn = blockIdx.x, bm = blockIdx.y;
    const int wm = (wid & 3) * 32;      // warp m-offset in tile
    const int wn = (wid >> 2) * 64;     // warp n-offset in tile

    float acc[2][8][4];
    #pragma unroll
    for (int i = 0; i < 2; i++)
        #pragma unroll
        for (int j = 0; j < 8; j++)
            #pragma unroll
            for (int q = 0; q < 4; q++) acc[i][j][q] = 0.f;

    // precomputed ldmatrix lane offsets (within-tile bytes, pre-swizzle row part)
    const int aRow = (lane & 15);            // + wm + mt*16
    const int aKb  = (lane >> 4) * 16;       // byte offset within 32B k-step
    const int bRow = ((lane >> 4) << 3) + (lane & 7);   // + wn + nt*16
    const int bKb  = ((lane >> 3) & 1) * 16;

    attn_fill(sb, 0, bm, bn, Ag, Bg, tid);
    CP_COMMIT();

    for (int c = 0; c < ATT_NCHUNK; c++) {
        if (c + 1 < ATT_NCHUNK) {
            attn_fill(sb + ((c + 1) & 1) * ATT_STG, c + 1, bm, bn, Ag, Bg, tid);
            CP_COMMIT();
            asm volatile("cp.async.wait_group 1;" ::: "memory");
        } else {
            asm volatile("cp.async.wait_group 0;" ::: "memory");
        }
        __syncthreads();

        const uint32_t aB = sb + (c & 1) * ATT_STG;
        const uint32_t bB = aB + ATT_BOFF;
        #pragma unroll
        for (int ks = 0; ks < 4; ks++) {
            uint32_t af[2][4];
            #pragma unroll
            for (int mt = 0; mt < 2; mt++) {
                int row = wm + mt * 16 + aRow;
                ldsm4(af[mt], aB + SW128((uint32_t)(row * 128 + ks * 32 + aKb)));
            }
            uint32_t bf[4][4];
            #pragma unroll
            for (int nt = 0; nt < 4; nt++) {
                int row = wn + nt * 16 + bRow;
                ldsm4(bf[nt], bB + SW128((uint32_t)(row * 128 + ks * 32 + bKb)));
            }
            #pragma unroll
            for (int mt = 0; mt < 2; mt++)
                #pragma unroll
                for (int n8 = 0; n8 < 8; n8++)
                    mma16816(acc[mt][n8], af[mt], &bf[n8 >> 1][(n8 & 1) * 2]);
        }
        __syncthreads();
    }

    // epilogue: direct float2 stores
    const int tig = lane & 3, gid = lane >> 2;
    #pragma unroll
    for (int mt = 0; mt < 2; mt++) {
        const int r0 = bm * 128 + wm + mt * 16 + gid;
        #pragma unroll
        for (int n8 = 0; n8 < 8; n8++) {
            const int cc = bn * 128 + wn + n8 * 8 + tig * 2;
            *reinterpret_cast<float2*>(P + (size_t)r0 * NN_ + cc)
                = make_float2(acc[mt][n8][0], acc[mt][n8][1]);
            *reinterpret_cast<float2*>(P + (size_t)(r0 + 8) * NN_ + cc)
                = make_float2(acc[mt][n8][2], acc[mt][n8][3]);
        }
    }
}

// ---------------- generic tiled SGEMM (fp32 SIMT) ----------------------------
template<bool TRANSB, bool DORELU>
__global__ void __launch_bounds__(256) sgemm_kernel(
    const float* __restrict__ A, const float* __restrict__ B,
    const float* __restrict__ bias, const float* __restrict__ addend,
    float* __restrict__ C, int M, int Nc, int Kd, float alpha)
{
    __shared__ float As[8][128];
    __shared__ float Bs[8][128];
    const int tid  = threadIdx.x;
    const int bx   = blockIdx.x * 128;
    const int by   = blockIdx.y * 128;
    const int row0 = (tid >> 4) * 8;
    const int col0 = (tid & 15) * 8;
    const int lRow = tid >> 1;
    const int lK   = (tid & 1) * 4;

    float acc[8][8];
    #pragma unroll
    for (int i = 0; i < 8; i++)
        #pragma unroll
        for (int j = 0; j < 8; j++) acc[i][j] = 0.f;

    for (int k0 = 0; k0 < Kd; k0 += 8) {
        float4 a = *reinterpret_cast<const float4*>(A + (size_t)(by + lRow) * Kd + k0 + lK);
        As[lK+0][lRow] = a.x; As[lK+1][lRow] = a.y; As[lK+2][lRow] = a.z; As[lK+3][lRow] = a.w;
        if (TRANSB) {
            float4 b = *reinterpret_cast<const float4*>(B + (size_t)(bx + lRow) * Kd + k0 + lK);
            Bs[lK+0][lRow] = b.x; Bs[lK+1][lRow] = b.y; Bs[lK+2][lRow] = b.z; Bs[lK+3][lRow] = b.w;
        } else {
            const int bK = tid >> 5;
            const int bC = (tid & 31) * 4;
            float4 b = *reinterpret_cast<const float4*>(B + (size_t)(k0 + bK) * Nc + bx + bC);
            *reinterpret_cast<float4*>(&Bs[bK][bC]) = b;
        }
        __syncthreads();
        #pragma unroll
        for (int kk = 0; kk < 8; kk++) {
            float4 a0 = *reinterpret_cast<const float4*>(&As[kk][row0]);
            float4 a1 = *reinterpret_cast<const float4*>(&As[kk][row0 + 4]);
            float4 b0 = *reinterpret_cast<const float4*>(&Bs[kk][col0]);
            float4 b1 = *reinterpret_cast<const float4*>(&Bs[kk][col0 + 4]);
            float ra[8] = {a0.x,a0.y,a0.z,a0.w,a1.x,a1.y,a1.z,a1.w};
            float rb[8] = {b0.x,b0.y,b0.z,b0.w,b1.x,b1.y,b1.z,b1.w};
            #pragma unroll
            for (int i = 0; i < 8; i++)
                #pragma unroll
                for (int j = 0; j < 8; j++)
                    acc[i][j] += ra[i] * rb[j];
        }
        __syncthreads();
    }

    #pragma unroll
    for (int i = 0; i < 8; i++) {
        const size_t r = (size_t)(by + row0 + i);
        #pragma unroll
        for (int j = 0; j < 8; j++) {
            const int c = bx + col0 + j;
            float v = acc[i][j] * alpha;
            if (bias)   v += bias[c];
            if (DORELU) v  = fmaxf(v, 0.f);
            if (addend) v += addend[r * Nc + c];
            C[r * Nc + c] = v;
        }
    }
}

// ---------------- per-row top-30 (iterative argmax) --------------------------
__global__ void __launch_bounds__(256) topk_kernel(const float* __restrict__ P,
                                                   int* __restrict__ tI,
                                                   float* __restrict__ tP)
{
    const int row  = blockIdx.x;
    const int tid  = threadIdx.x;
    const int lane = tid & 31, w = tid >> 5;
    const float* p = P + (size_t)row * NN_;

    float v[32];
    #pragma unroll
    for (int j = 0; j < 32; j++) v[j] = p[tid + j * 256];

    __shared__ float sV[8];
    __shared__ int   sI[9];
    __shared__ float selV[KT_];
    __shared__ int   selI[KT_];

    for (int it = 0; it < KT_; it++) {
        float bv = v[0]; int bj = 0;
        #pragma unroll
        for (int j = 1; j < 32; j++) if (v[j] > bv) { bv = v[j]; bj = j; }
        int bi = tid + bj * 256;
        #pragma unroll
        for (int off = 16; off; off >>= 1) {
            float ov = __shfl_xor_sync(0xffffffffu, bv, off);
            int   oi = __shfl_xor_sync(0xffffffffu, bi, off);
            if (ov > bv || (ov == bv && oi < bi)) { bv = ov; bi = oi; }
        }
        if (lane == 0) { sV[w] = bv; sI[w] = bi; }
        __syncthreads();
        if (tid == 0) {
            float Bv = sV[0]; int Bi = sI[0];
            #pragma unroll
            for (int q = 1; q < 8; q++)
                if (sV[q] > Bv || (sV[q] == Bv && sI[q] < Bi)) { Bv = sV[q]; Bi = sI[q]; }
            selV[it] = Bv; selI[it] = Bi; sI[8] = Bi;
        }
        __syncthreads();
        const int win = sI[8];
        if ((win & 255) == tid) {
            const int jj = win >> 8;
            #pragma unroll
            for (int j = 0; j < 32; j++) if (j == jj) v[j] = -CUDART_INF_F;
        }
    }
    __syncthreads();
    if (tid < 32) {
        float ev = (tid < KT_) ? expf(selV[tid] - selV[0]) : 0.f;
        float s = ev;
        #pragma unroll
        for (int off = 16; off; off >>= 1) s += __shfl_xor_sync(0xffffffffu, s, off);
        if (tid < KT_) {
            tP[row * KT_ + tid] = ev / s;
            tI[row * KT_ + tid] = selI[tid];
        }
    }
}

// ---------------- fused neighbor aggregation per row ------------------------
__global__ void __launch_bounds__(256) neighbor_kernel(
    const float* __restrict__ eH, const float* __restrict__ eT,
    const int* __restrict__ tI, const float* __restrict__ tP,
    float* __restrict__ U, float* __restrict__ V)
{
    const int row  = blockIdx.x;
    const int d    = threadIdx.x;
    const int lane = d & 31, w = d >> 5;

    __shared__ float sNb[KT_][DD_];
    __shared__ float sEh[DD_];
    __shared__ float sP[KT_];
    __shared__ int   sIdx[KT_];
    __shared__ float sW[KT_];
    __shared__ float sPr[KT_];

    const float eh = eH[(size_t)row * DD_ + d];
    sEh[d] = eh;
    if (d < KT_) { sP[d] = tP[row * KT_ + d]; sIdx[d] = tI[row * KT_ + d]; }
    __syncthreads();

    #pragma unroll
    for (int k = 0; k < KT_; k++) sNb[k][d] = eT[(size_t)sIdx[k] * DD_ + d];
    __syncthreads();

    for (int k = w; k < KT_; k += 8) {
        const float pk = sP[k], ck = 2.f - pk;
        float snb = 0.f, sg = 0.f;
        #pragma unroll
        for (int q = 0; q < 8; q++) {
            const int dd = lane + q * 32;
            const float nb = sNb[k][dd];
            snb += nb;
            sg  += tanhf(ck * sEh[dd] + pk * nb);
        }
        #pragma unroll
        for (int off = 16; off; off >>= 1) {
            snb += __shfl_xor_sync(0xffffffffu, snb, off);
            sg  += __shfl_xor_sync(0xffffffffu, sg,  off);
        }
        if (lane == 0) sW[k] = snb * sg;
    }
    __syncthreads();

    if (d < 32) {
        float val = (d < KT_) ? sW[d] : -CUDART_INF_F;
        float m = val;
        #pragma unroll
        for (int off = 16; off; off >>= 1) m = fmaxf(m, __shfl_xor_sync(0xffffffffu, m, off));
        float ev = (d < KT_) ? expf(val - m) : 0.f;
        float s = ev;
        #pragma unroll
        for (int off = 16; off; off >>= 1) s += __shfl_xor_sync(0xffffffffu, s, off);
        if (d < KT_) sPr[d] = ev / s;
    }
    __syncthreads();

    float acc = 0.f;
    #pragma unroll
    for (int k = 0; k < KT_; k++) acc += sPr[k] * sNb[k][d];
    U[(size_t)row * DD_ + d] = eh + acc;
    V[(size_t)row * DD_ + d] = eh * acc;
}

// ---------------- attention head ---------------------------------------------
__global__ void __launch_bounds__(128) att_kernel(
    const float* __restrict__ E, const float* __restrict__ W1,
    const float* __restrict__ b1, const float* __restrict__ W2,
    const float* __restrict__ b2, float* __restrict__ att)
{
    const int r0 = blockIdx.x * 16;
    const int j  = threadIdx.x;
    __shared__ float sE[16][DD_];
    for (int t = j; t < 16 * DD_; t += 128)
        sE[t >> 8][t & 255] = E[(size_t)(r0 + (t >> 8)) * DD_ + (t & 255)];
    __syncthreads();

    float acc[16];
    #pragma unroll
    for (int r = 0; r < 16; r++) acc[r] = 0.f;
    for (int dd = 0; dd < DD_; dd++) {
        const float wv = W1[dd * 128 + j];
        #pragma unroll
        for (int r = 0; r < 16; r++) acc[r] += sE[r][dd] * wv;
    }
    const float bb = b1[j], w2 = W2[j];
    __shared__ float sRed[16][4];
    const int lane = j & 31, w = j >> 5;
    #pragma unroll
    for (int r = 0; r < 16; r++) {
        float val = acc[r] + bb;
        val = (val > 0.f) ? val : 0.01f * val;
        val *= w2;
        #pragma unroll
        for (int off = 16; off; off >>= 1) val += __shfl_xor_sync(0xffffffffu, val, off);
        if (lane == 0) sRed[r][w] = val;
    }
    __syncthreads();
    if (j < 16) att[r0 + j] = sRed[j][0] + sRed[j][1] + sRed[j][2] + sRed[j][3] + b2[0];
}

// ---------------- softmax-over-nodes reduction -------------------------------
__global__ void __launch_bounds__(1024) smred_kernel(const float* __restrict__ att,
                                                     float* __restrict__ red)
{
    const int tid = threadIdx.x;
    __shared__ float s[32];
    float m = -CUDART_INF_F;
    for (int i = tid; i < NN_; i += 1024) m = fmaxf(m, att[i]);
    #pragma unroll
    for (int off = 16; off; off >>= 1) m = fmaxf(m, __shfl_xor_sync(0xffffffffu, m, off));
    if ((tid & 31) == 0) s[tid >> 5] = m;
    __syncthreads();
    if (tid < 32) {
        float mm = s[tid];
        #pragma unroll
        for (int off = 16; off; off >>= 1) mm = fmaxf(mm, __shfl_xor_sync(0xffffffffu, mm, off));
        if (tid == 0) s[0] = mm;
    }
    __syncthreads();
    const float M = s[0];
    __syncthreads();
    float z = 0.f;
    for (int i = tid; i < NN_; i += 1024) z += expf(att[i] - M);
    #pragma unroll
    for (int off = 16; off; off >>= 1) z += __shfl_xor_sync(0xffffffffu, z, off);
    if ((tid & 31) == 0) s[tid >> 5] = z;
    __syncthreads();
    if (tid < 32) {
        float zz = s[tid];
        #pragma unroll
        for (int off = 16; off; off >>= 1) zz += __shfl_xor_sync(0xffffffffu, zz, off);
        if (tid == 0) { red[0] = M; red[1] = zz; }
    }
}

__global__ void __launch_bounds__(256) egpart_kernel(const float* __restrict__ att,
    const float* __restrict__ E, const float* __restrict__ red, float* __restrict__ part)
{
    const int b = blockIdx.x;
    const int d = threadIdx.x;
    __shared__ float wsh[256];
    wsh[d] = expf(att[b * 256 + d] - red[0]);
    __syncthreads();
    float acc = 0.f;
    const float* Eb = E + (size_t)b * 256 * DD_;
    for (int i = 0; i < 256; i++) acc += wsh[i] * Eb[(size_t)i * DD_ + d];
    part[b * DD_ + d] = acc;
}

__global__ void __launch_bounds__(256) egfin_kernel(const float* __restrict__ part,
    const float* __restrict__ red, float* __restrict__ eg)
{
    const int d = threadIdx.x;
    float s = 0.f;
    #pragma unroll
    for (int b = 0; b < 32; b++) s += part[b * DD_ + d];
    eg[d] = s / red[1];
}

// ---------------- launcher ---------------------------------------------------
extern "C" void kernel_launch(void* const* d_in, const int* in_sizes, int n_in,
                              void* d_out, int out_size)
{
    const float* x    = (const float*)d_in[0];
    const float* Wfc1 = (const float*)d_in[1];
    const float* bfc1 = (const float*)d_in[2];
    const float* Wfc2 = (const float*)d_in[3];
    const float* bfc2 = (const float*)d_in[4];
    const float* Whd  = (const float*)d_in[5];
    const float* bhd  = (const float*)d_in[6];
    const float* Wtl  = (const float*)d_in[7];
    const float* btl  = (const float*)d_in[8];
    const float* Wl1  = (const float*)d_in[9];
    const float* bl1  = (const float*)d_in[10];
    const float* Wl2  = (const float*)d_in[11];
    const float* bl2  = (const float*)d_in[12];
    const float* Wa1  = (const float*)d_in[13];
    const float* ba1  = (const float*)d_in[14];
    const float* Wa2  = (const float*)d_in[15];
    const float* ba2  = (const float*)d_in[16];

    float *P, *h1, *h, *eh, *et, *U, *V, *E1, *att, *red, *part, *tP;
    __nv_bfloat16 *Abf, *Bbf;
    int* tI;
    cudaGetSymbolAddress((void**)&P,    g_P);
    cudaGetSymbolAddress((void**)&h1,   g_h1);
    cudaGetSymbolAddress((void**)&h,    g_h);
    cudaGetSymbolAddress((void**)&eh,   g_eh);
    cudaGetSymbolAddress((void**)&et,   g_et);
    cudaGetSymbolAddress((void**)&U,    g_U);
    cudaGetSymbolAddress((void**)&V,    g_V);
    cudaGetSymbolAddress((void**)&E1,   g_E1);
    cudaGetSymbolAddress((void**)&att,  g_att);
    cudaGetSymbolAddress((void**)&red,  g_red);
    cudaGetSymbolAddress((void**)&part, g_part);
    cudaGetSymbolAddress((void**)&tI,   g_tI);
    cudaGetSymbolAddress((void**)&tP,   g_tP);
    cudaGetSymbolAddress((void**)&Abf,  g_Abf);
    cudaGetSymbolAddress((void**)&Bbf,  g_Bbf);

    cudaFuncSetAttribute(attn_mma_kernel,
                         cudaFuncAttributeMaxDynamicSharedMemorySize, 2 * ATT_STG);

    float* out = (float*)d_out;
    const size_t ND = (size_t)NN_ * DD_;
    float* e_out;
    float* eg_out;
    if ((size_t)out_size >= ND + DD_)      { e_out = out; eg_out = out + ND; }
    else if ((size_t)out_size >= ND)       { e_out = out; eg_out = nullptr;  }
    else                                   { e_out = h1;  eg_out = out;      }

    const dim3 gSmall(DD_ / 128, NN_ / 128);   // (2, 64)

    // MLP trunk (fp32 SIMT for now)
    sgemm_kernel<false, true ><<<gSmall, 256>>>(x,  Wfc1, bfc1, nullptr, h1, NN_, DD_, DIN_, 1.f);
    sgemm_kernel<false, true ><<<gSmall, 256>>>(h1, Wfc2, bfc2, nullptr, h,  NN_, DD_, DD_,  1.f);
    sgemm_kernel<false, false><<<gSmall, 256>>>(h,  Whd,  bhd,  nullptr, eh, NN_, DD_, DD_,  1.f);
    sgemm_kernel<false, false><<<gSmall, 256>>>(h,  Wtl,  btl,  nullptr, et, NN_, DD_, DD_,  1.f);

    // pairwise logits via warp-MMA bf16 hi/lo split (fp32-accurate)
    split_kernel<<<NN_, 256>>>(eh, et, Abf, Bbf);
    attn_mma_kernel<<<dim3(NN_/128, NN_/128), 256, 2 * ATT_STG>>>(Abf, Bbf, P);

    topk_kernel    <<<NN_, 256>>>(P, tI, tP);
    neighbor_kernel<<<NN_, 256>>>(eh, et, tI, tP, U, V);

    // e = relu(U@Wl1+b) + relu(V@Wl2+b)
    sgemm_kernel<false, true ><<<gSmall, 256>>>(U, Wl1, bl1, nullptr, E1,    NN_, DD_, DD_, 1.f);
    sgemm_kernel<false, true ><<<gSmall, 256>>>(V, Wl2, bl2, E1,      e_out, NN_, DD_, DD_, 1.f);

    if (eg_out) {
        att_kernel   <<<NN_ / 16, 128>>>(e_out, Wa1, ba1, Wa2, ba2, att);
        smred_kernel <<<1, 1024>>>(att, red);
        egpart_kernel<<<32, 256>>>(att, e_out, red, part);
        egfin_kernel <<<1, 256>>>(part, red, eg_out);
    }
}

// round 4
// speedup vs baseline: 1.8100x; 1.2100x over previous
#include <cuda_runtime.h>
#include <cuda_bf16.h>
#include <math_constants.h>
#include <cstdint>

#define NN_  8192
#define DIN_ 1024
#define DD_  256
#define KT_  30
#define KA3_ 768    // 3-term split row length (attn operands)
#define KA4_ 1024   // 4-term split row length (trunk operands)
#define KAX_ 4096   // 4-term split of x (K=1024)

// ---------------- scratch (static device globals: allocation-free) ----------
__device__ float g_P[(size_t)NN_ * NN_];     // attn logits [N,N]  (256 MB)
__device__ float g_eh[NN_ * DD_];
__device__ float g_et[NN_ * DD_];
__device__ float g_E1[NN_ * DD_];
__device__ float g_spill[NN_ * DD_];         // e sink when out_size is small
__device__ __nv_bfloat16 g_Xbf [(size_t)NN_ * KAX_];  // 64 MB: x 4-term A-split
__device__ __nv_bfloat16 g_h1b [(size_t)NN_ * KA4_];  // 16 MB
__device__ __nv_bfloat16 g_hb  [(size_t)NN_ * KA4_];
__device__ __nv_bfloat16 g_ehs [(size_t)NN_ * KA3_];  // 12 MB (A3, scaled)
__device__ __nv_bfloat16 g_ets [(size_t)NN_ * KA3_];  // 12 MB (B3)
__device__ __nv_bfloat16 g_Ub  [(size_t)NN_ * KA4_];
__device__ __nv_bfloat16 g_Vb  [(size_t)NN_ * KA4_];
__device__ __nv_bfloat16 g_Wfc1b[(size_t)DD_ * KAX_]; // 2 MB  (B4 layout)
__device__ __nv_bfloat16 g_Wfc2b[DD_ * KA4_];
__device__ __nv_bfloat16 g_Whdb [DD_ * KA4_];
__device__ __nv_bfloat16 g_Wtlb [DD_ * KA4_];
__device__ __nv_bfloat16 g_Wl1b [DD_ * KA4_];
__device__ __nv_bfloat16 g_Wl2b [DD_ * KA4_];
__device__ int   g_tI[NN_ * KT_];
__device__ float g_tP[NN_ * KT_];
__device__ float g_att[NN_];
__device__ float g_red[2];
__device__ float g_part[32 * DD_];

// =================== warp-MMA helpers (sm_80+, compute_103-safe) ============
__device__ __forceinline__ uint32_t smem_u32(const void* p) {
    uint32_t a;
    asm("{ .reg .u64 t; cvta.to.shared.u64 t, %1; cvt.u32.u64 %0, t; }" : "=r"(a) : "l"(p));
    return a;
}
#define SW128(off) ((off) ^ (((off) >> 3) & 0x70))
#define CP16(dst, src)    asm volatile("cp.async.cg.shared.global [%0], [%1], 16;" :: "r"(dst), "l"(src) : "memory")
#define CP_COMMIT()       asm volatile("cp.async.commit_group;" ::: "memory")

__device__ __forceinline__ void ldsm4(uint32_t* r, uint32_t addr) {
    asm volatile("ldmatrix.sync.aligned.m8n8.x4.shared.b16 {%0,%1,%2,%3}, [%4];"
        : "=r"(r[0]), "=r"(r[1]), "=r"(r[2]), "=r"(r[3]) : "r"(addr));
}
__device__ __forceinline__ void mma16816(float* d, const uint32_t* a, const uint32_t* b) {
    asm volatile("mma.sync.aligned.m16n8k16.row.col.f32.bf16.bf16.f32 "
        "{%0,%1,%2,%3}, {%4,%5,%6,%7}, {%8,%9}, {%0,%1,%2,%3};"
        : "+f"(d[0]), "+f"(d[1]), "+f"(d[2]), "+f"(d[3])
        : "r"(a[0]), "r"(a[1]), "r"(a[2]), "r"(a[3]), "r"(b[0]), "r"(b[1]));
}

// ---------------- input / weight split prep ---------------------------------
// x [N][1024] -> Xbf [N][4096] A4 = [hi | lo | hi | lo]
__global__ void __launch_bounds__(256) xsplit_kernel(const float* __restrict__ x,
                                                     __nv_bfloat16* __restrict__ X)
{
    const int r = blockIdx.x;
    #pragma unroll
    for (int q = 0; q < 4; q++) {
        const int c = threadIdx.x + q * 256;
        float v = x[(size_t)r * DIN_ + c];
        __nv_bfloat16 h = __float2bfloat16(v);
        __nv_bfloat16 l = __float2bfloat16(v - __bfloat162float(h));
        __nv_bfloat16* row = X + (size_t)r * KAX_;
        row[c] = h; row[DIN_ + c] = l; row[2*DIN_ + c] = h; row[3*DIN_ + c] = l;
    }
}
// W [K][256] -> Wb [256][4K] B4 = [hi | hi | lo | lo] (transposed)
__global__ void __launch_bounds__(256) wprep_kernel(const float* __restrict__ W,
                                                    __nv_bfloat16* __restrict__ Wb, int K)
{
    const int k = blockIdx.x;
    const int n = threadIdx.x;
    float v = W[(size_t)k * DD_ + n];
    __nv_bfloat16 h = __float2bfloat16(v);
    __nv_bfloat16 l = __float2bfloat16(v - __bfloat162float(h));
    __nv_bfloat16* row = Wb + (size_t)n * (4 * K);
    row[k] = h; row[K + k] = h; row[2*K + k] = l; row[3*K + k] = l;
}

// ---------------- shared tile fill (A/B both [rows][Ka] row-major bf16) -----
__device__ __forceinline__ void tile_fill(uint32_t sbase, int kc, int bm, int bn,
    const __nv_bfloat16* __restrict__ Ag, const __nv_bfloat16* __restrict__ Bg,
    int tid, int Ka)
{
    #pragma unroll
    for (int i = 0; i < 4; i++) {               // A: 128 rows x 128B
        int q = tid + i * 256;
        int row = q >> 3, c = q & 7;
        const __nv_bfloat16* src = Ag + (size_t)(bm * 128 + row) * Ka + kc * 64 + c * 8;
        CP16(sbase + SW128((uint32_t)(row * 128 + c * 16)), src);
    }
    #pragma unroll
    for (int i = 0; i < 4; i++) {               // B: 128 rows x 128B
        int q = tid + i * 256;
        int row = q >> 3, c = q & 7;
        const __nv_bfloat16* src = Bg + (size_t)(bn * 128 + row) * Ka + kc * 64 + c * 8;
        CP16(sbase + 16384 + SW128((uint32_t)(row * 128 + c * 16)), src);
    }
}

// ---------------- MMA mainloop core (BM=BN=128, BK=64, 8 warps 4x2) ---------
#define MMA_STG 32768
struct MmaAcc { float a[2][8][4]; };

__device__ __forceinline__ void mma_mainloop(MmaAcc& A_, uint32_t sb, int nchunk,
    int bm, int bn, const __nv_bfloat16* Ag, const __nv_bfloat16* Bg, int Ka,
    int tid, int wid, int lane)
{
    const int wm = (wid & 3) * 32;
    const int wn = (wid >> 2) * 64;
    const int aRow = (lane & 15);
    const int aKb  = (lane >> 4) * 16;
    const int bRow = ((lane >> 4) << 3) + (lane & 7);
    const int bKb  = ((lane >> 3) & 1) * 16;

    tile_fill(sb, 0, bm, bn, Ag, Bg, tid, Ka);
    CP_COMMIT();

    for (int c = 0; c < nchunk; c++) {
        if (c + 1 < nchunk) {
            tile_fill(sb + ((c + 1) & 1) * MMA_STG, c + 1, bm, bn, Ag, Bg, tid, Ka);
            CP_COMMIT();
            asm volatile("cp.async.wait_group 1;" ::: "memory");
        } else {
            asm volatile("cp.async.wait_group 0;" ::: "memory");
        }
        __syncthreads();

        const uint32_t aB = sb + (c & 1) * MMA_STG;
        const uint32_t bB = aB + 16384;
        #pragma unroll
        for (int ks = 0; ks < 4; ks++) {
            uint32_t af[2][4];
            #pragma unroll
            for (int mt = 0; mt < 2; mt++) {
                int row = wm + mt * 16 + aRow;
                ldsm4(af[mt], aB + SW128((uint32_t)(row * 128 + ks * 32 + aKb)));
            }
            uint32_t bf[4][4];
            #pragma unroll
            for (int nt = 0; nt < 4; nt++) {
                int row = wn + nt * 16 + bRow;
                ldsm4(bf[nt], bB + SW128((uint32_t)(row * 128 + ks * 32 + bKb)));
            }
            #pragma unroll
            for (int mt = 0; mt < 2; mt++)
                #pragma unroll
                for (int n8 = 0; n8 < 8; n8++)
                    mma16816(A_.a[mt][n8], af[mt], &bf[n8 >> 1][(n8 & 1) * 2]);
        }
        __syncthreads();
    }
}

// ---------------- attn GEMM: P = ehs(A3) @ ets(B3)^T ------------------------
__global__ void __launch_bounds__(256, 2) attn_mma_kernel(
    const __nv_bfloat16* __restrict__ Ag, const __nv_bfloat16* __restrict__ Bg,
    float* __restrict__ P)
{
    extern __shared__ char smem[];
    const uint32_t sb = smem_u32(smem);
    const int tid = threadIdx.x, wid = tid >> 5, lane = tid & 31;
    const int bn = blockIdx.x, bm = blockIdx.y;

    MmaAcc acc;
    #pragma unroll
    for (int i = 0; i < 2; i++)
        #pragma unroll
        for (int j = 0; j < 8; j++)
            #pragma unroll
            for (int q = 0; q < 4; q++) acc.a[i][j][q] = 0.f;

    mma_mainloop(acc, sb, KA3_ / 64, bm, bn, Ag, Bg, KA3_, tid, wid, lane);

    const int wm = (wid & 3) * 32, wn = (wid >> 2) * 64;
    const int tig = lane & 3, gid = lane >> 2;
    #pragma unroll
    for (int mt = 0; mt < 2; mt++) {
        const int r0 = bm * 128 + wm + mt * 16 + gid;
        #pragma unroll
        for (int n8 = 0; n8 < 8; n8++) {
            const int cc = bn * 128 + wn + n8 * 8 + tig * 2;
            *reinterpret_cast<float2*>(P + (size_t)r0 * NN_ + cc)
                = make_float2(acc.a[mt][n8][0], acc.a[mt][n8][1]);
            *reinterpret_cast<float2*>(P + (size_t)(r0 + 8) * NN_ + cc)
                = make_float2(acc.a[mt][n8][2], acc.a[mt][n8][3]);
        }
    }
}

// ---------------- trunk GEMM with fused split epilogues ---------------------
// OSPL: 0 none, 1 A4 [h|l|h|l], 2 A3-scaled [h|l|h], 3 B3 [h|h|l]
template<int OSPL, bool RELU, bool HASADD>
__global__ void __launch_bounds__(256, 2) mma_gemm_kernel(
    const __nv_bfloat16* __restrict__ Ag, const __nv_bfloat16* __restrict__ Bg,
    const float* __restrict__ bias, const float* __restrict__ addend,
    float* __restrict__ C, __nv_bfloat16* __restrict__ S, int Ka, float scale)
{
    extern __shared__ char smem[];
    const uint32_t sb = smem_u32(smem);
    const int tid = threadIdx.x, wid = tid >> 5, lane = tid & 31;
    const int bn = blockIdx.x, bm = blockIdx.y;

    MmaAcc acc;
    #pragma unroll
    for (int i = 0; i < 2; i++)
        #pragma unroll
        for (int j = 0; j < 8; j++)
            #pragma unroll
            for (int q = 0; q < 4; q++) acc.a[i][j][q] = 0.f;

    mma_mainloop(acc, sb, Ka / 64, bm, bn, Ag, Bg, Ka, tid, wid, lane);

    const int wm = (wid & 3) * 32, wn = (wid >> 2) * 64;
    const int tig = lane & 3, gid = lane >> 2;
    #pragma unroll
    for (int mt = 0; mt < 2; mt++) {
        #pragma unroll
        for (int n8 = 0; n8 < 8; n8++) {
            const int cc = bn * 128 + wn + n8 * 8 + tig * 2;
            #pragma unroll
            for (int hh = 0; hh < 2; hh++) {
                const int r = bm * 128 + wm + mt * 16 + gid + hh * 8;
                #pragma unroll
                for (int e = 0; e < 2; e++) {
                    const int c = cc + e;
                    float v = acc.a[mt][n8][hh * 2 + e] + bias[c];
                    if (RELU)   v = fmaxf(v, 0.f);
                    if (HASADD) v += addend[(size_t)r * DD_ + c];
                    if (C) C[(size_t)r * DD_ + c] = v;
                    if (OSPL == 1) {
                        __nv_bfloat16 h = __float2bfloat16(v);
                        __nv_bfloat16 l = __float2bfloat16(v - __bfloat162float(h));
                        __nv_bfloat16* row = S + (size_t)r * KA4_;
                        row[c] = h; row[DD_ + c] = l; row[2*DD_ + c] = h; row[3*DD_ + c] = l;
                    } else if (OSPL == 2) {
                        float vs = v * scale;
                        __nv_bfloat16 h = __float2bfloat16(vs);
                        __nv_bfloat16 l = __float2bfloat16(vs - __bfloat162float(h));
                        __nv_bfloat16* row = S + (size_t)r * KA3_;
                        row[c] = h; row[DD_ + c] = l; row[2*DD_ + c] = h;
                    } else if (OSPL == 3) {
                        __nv_bfloat16 h = __float2bfloat16(v);
                        __nv_bfloat16 l = __float2bfloat16(v - __bfloat162float(h));
                        __nv_bfloat16* row = S + (size_t)r * KA3_;
                        row[c] = h; row[DD_ + c] = h; row[2*DD_ + c] = l;
                    }
                }
            }
        }
    }
}

// ---------------- per-row top-30 (iterative argmax) --------------------------
__global__ void __launch_bounds__(256) topk_kernel(const float* __restrict__ P,
                                                   int* __restrict__ tI,
                                                   float* __restrict__ tP)
{
    const int row  = blockIdx.x;
    const int tid  = threadIdx.x;
    const int lane = tid & 31, w = tid >> 5;
    const float* p = P + (size_t)row * NN_;

    float v[32];
    #pragma unroll
    for (int j = 0; j < 32; j++) v[j] = p[tid + j * 256];

    __shared__ float sV[8];
    __shared__ int   sI[9];
    __shared__ float selV[KT_];
    __shared__ int   selI[KT_];

    for (int it = 0; it < KT_; it++) {
        float bv = v[0]; int bj = 0;
        #pragma unroll
        for (int j = 1; j < 32; j++) if (v[j] > bv) { bv = v[j]; bj = j; }
        int bi = tid + bj * 256;
        #pragma unroll
        for (int off = 16; off; off >>= 1) {
            float ov = __shfl_xor_sync(0xffffffffu, bv, off);
            int   oi = __shfl_xor_sync(0xffffffffu, bi, off);
            if (ov > bv || (ov == bv && oi < bi)) { bv = ov; bi = oi; }
        }
        if (lane == 0) { sV[w] = bv; sI[w] = bi; }
        __syncthreads();
        if (tid == 0) {
            float Bv = sV[0]; int Bi = sI[0];
            #pragma unroll
            for (int q = 1; q < 8; q++)
                if (sV[q] > Bv || (sV[q] == Bv && sI[q] < Bi)) { Bv = sV[q]; Bi = sI[q]; }
            selV[it] = Bv; selI[it] = Bi; sI[8] = Bi;
        }
        __syncthreads();
        const int win = sI[8];
        if ((win & 255) == tid) {
            const int jj = win >> 8;
            #pragma unroll
            for (int j = 0; j < 32; j++) if (j == jj) v[j] = -CUDART_INF_F;
        }
    }
    __syncthreads();
    if (tid < 32) {
        float ev = (tid < KT_) ? expf(selV[tid] - selV[0]) : 0.f;
        float s = ev;
        #pragma unroll
        for (int off = 16; off; off >>= 1) s += __shfl_xor_sync(0xffffffffu, s, off);
        if (tid < KT_) {
            tP[row * KT_ + tid] = ev / s;
            tI[row * KT_ + tid] = selI[tid];
        }
    }
}

// ---------------- fused neighbor aggregation per row ------------------------
// Emits U, V directly as A4 splits for lin1/lin2.
__global__ void __launch_bounds__(256) neighbor_kernel(
    const float* __restrict__ eH, const float* __restrict__ eT,
    const int* __restrict__ tI, const float* __restrict__ tP,
    __nv_bfloat16* __restrict__ Ub, __nv_bfloat16* __restrict__ Vb)
{
    const int row  = blockIdx.x;
    const int d    = threadIdx.x;
    const int lane = d & 31, w = d >> 5;

    __shared__ float sNb[KT_][DD_];
    __shared__ float sEh[DD_];
    __shared__ float sP[KT_];
    __shared__ int   sIdx[KT_];
    __shared__ float sW[KT_];
    __shared__ float sPr[KT_];

    const float eh = eH[(size_t)row * DD_ + d];
    sEh[d] = eh;
    if (d < KT_) { sP[d] = tP[row * KT_ + d]; sIdx[d] = tI[row * KT_ + d]; }
    __syncthreads();

    #pragma unroll
    for (int k = 0; k < KT_; k++) sNb[k][d] = eT[(size_t)sIdx[k] * DD_ + d];
    __syncthreads();

    for (int k = w; k < KT_; k += 8) {
        const float pk = sP[k], ck = 2.f - pk;
        float snb = 0.f, sg = 0.f;
        #pragma unroll
        for (int q = 0; q < 8; q++) {
            const int dd = lane + q * 32;
            const float nb = sNb[k][dd];
            snb += nb;
            sg  += tanhf(ck * sEh[dd] + pk * nb);
        }
        #pragma unroll
        for (int off = 16; off; off >>= 1) {
            snb += __shfl_xor_sync(0xffffffffu, snb, off);
            sg  += __shfl_xor_sync(0xffffffffu, sg,  off);
        }
        if (lane == 0) sW[k] = snb * sg;
    }
    __syncthreads();

    if (d < 32) {
        float val = (d < KT_) ? sW[d] : -CUDART_INF_F;
        float m = val;
        #pragma unroll
        for (int off = 16; off; off >>= 1) m = fmaxf(m, __shfl_xor_sync(0xffffffffu, m, off));
        float ev = (d < KT_) ? expf(val - m) : 0.f;
        float s = ev;
        #pragma unroll
        for (int off = 16; off; off >>= 1) s += __shfl_xor_sync(0xffffffffu, s, off);
        if (d < KT_) sPr[d] = ev / s;
    }
    __syncthreads();

    float acc = 0.f;
    #pragma unroll
    for (int k = 0; k < KT_; k++) acc += sPr[k] * sNb[k][d];

    const float u = eh + acc, vv = eh * acc;
    {
        __nv_bfloat16 h = __float2bfloat16(u);
        __nv_bfloat16 l = __float2bfloat16(u - __bfloat162float(h));
        __nv_bfloat16* rw = Ub + (size_t)row * KA4_;
        rw[d] = h; rw[DD_ + d] = l; rw[2*DD_ + d] = h; rw[3*DD_ + d] = l;
    }
    {
        __nv_bfloat16 h = __float2bfloat16(vv);
        __nv_bfloat16 l = __float2bfloat16(vv - __bfloat162float(h));
        __nv_bfloat16* rw = Vb + (size_t)row * KA4_;
        rw[d] = h; rw[DD_ + d] = l; rw[2*DD_ + d] = h; rw[3*DD_ + d] = l;
    }
}

// ---------------- attention head ---------------------------------------------
__global__ void __launch_bounds__(128) att_kernel(
    const float* __restrict__ E, const float* __restrict__ W1,
    const float* __restrict__ b1, const float* __restrict__ W2,
    const float* __restrict__ b2, float* __restrict__ att)
{
    const int r0 = blockIdx.x * 16;
    const int j  = threadIdx.x;
    __shared__ float sE[16][DD_];
    for (int t = j; t < 16 * DD_; t += 128)
        sE[t >> 8][t & 255] = E[(size_t)(r0 + (t >> 8)) * DD_ + (t & 255)];
    __syncthreads();

    float acc[16];
    #pragma unroll
    for (int r = 0; r < 16; r++) acc[r] = 0.f;
    for (int dd = 0; dd < DD_; dd++) {
        const float wv = W1[dd * 128 + j];
        #pragma unroll
        for (int r = 0; r < 16; r++) acc[r] += sE[r][dd] * wv;
    }
    const float bb = b1[j], w2 = W2[j];
    __shared__ float sRed[16][4];
    const int lane = j & 31, w = j >> 5;
    #pragma unroll
    for (int r = 0; r < 16; r++) {
        float val = acc[r] + bb;
        val = (val > 0.f) ? val : 0.01f * val;
        val *= w2;
        #pragma unroll
        for (int off = 16; off; off >>= 1) val += __shfl_xor_sync(0xffffffffu, val, off);
        if (lane == 0) sRed[r][w] = val;
    }
    __syncthreads();
    if (j < 16) att[r0 + j] = sRed[j][0] + sRed[j][1] + sRed[j][2] + sRed[j][3] + b2[0];
}

// ---------------- softmax-over-nodes reduction -------------------------------
__global__ void __launch_bounds__(1024) smred_kernel(const float* __restrict__ att,
                                                     float* __restrict__ red)
{
    const int tid = threadIdx.x;
    __shared__ float s[32];
    float m = -CUDART_INF_F;
    for (int i = tid; i < NN_; i += 1024) m = fmaxf(m, att[i]);
    #pragma unroll
    for (int off = 16; off; off >>= 1) m = fmaxf(m, __shfl_xor_sync(0xffffffffu, m, off));
    if ((tid & 31) == 0) s[tid >> 5] = m;
    __syncthreads();
    if (tid < 32) {
        float mm = s[tid];
        #pragma unroll
        for (int off = 16; off; off >>= 1) mm = fmaxf(mm, __shfl_xor_sync(0xffffffffu, mm, off));
        if (tid == 0) s[0] = mm;
    }
    __syncthreads();
    const float M = s[0];
    __syncthreads();
    float z = 0.f;
    for (int i = tid; i < NN_; i += 1024) z += expf(att[i] - M);
    #pragma unroll
    for (int off = 16; off; off >>= 1) z += __shfl_xor_sync(0xffffffffu, z, off);
    if ((tid & 31) == 0) s[tid >> 5] = z;
    __syncthreads();
    if (tid < 32) {
        float zz = s[tid];
        #pragma unroll
        for (int off = 16; off; off >>= 1) zz += __shfl_xor_sync(0xffffffffu, zz, off);
        if (tid == 0) { red[0] = M; red[1] = zz; }
    }
}

__global__ void __launch_bounds__(256) egpart_kernel(const float* __restrict__ att,
    const float* __restrict__ E, const float* __restrict__ red, float* __restrict__ part)
{
    const int b = blockIdx.x;
    const int d = threadIdx.x;
    __shared__ float wsh[256];
    wsh[d] = expf(att[b * 256 + d] - red[0]);
    __syncthreads();
    float acc = 0.f;
    const float* Eb = E + (size_t)b * 256 * DD_;
    for (int i = 0; i < 256; i++) acc += wsh[i] * Eb[(size_t)i * DD_ + d];
    part[b * DD_ + d] = acc;
}

__global__ void __launch_bounds__(256) egfin_kernel(const float* __restrict__ part,
    const float* __restrict__ red, float* __restrict__ eg)
{
    const int d = threadIdx.x;
    float s = 0.f;
    #pragma unroll
    for (int b = 0; b < 32; b++) s += part[b * DD_ + d];
    eg[d] = s / red[1];
}

// ---------------- launcher ---------------------------------------------------
extern "C" void kernel_launch(void* const* d_in, const int* in_sizes, int n_in,
                              void* d_out, int out_size)
{
    const float* x    = (const float*)d_in[0];
    const float* Wfc1 = (const float*)d_in[1];
    const float* bfc1 = (const float*)d_in[2];
    const float* Wfc2 = (const float*)d_in[3];
    const float* bfc2 = (const float*)d_in[4];
    const float* Whd  = (const float*)d_in[5];
    const float* bhd  = (const float*)d_in[6];
    const float* Wtl  = (const float*)d_in[7];
    const float* btl  = (const float*)d_in[8];
    const float* Wl1  = (const float*)d_in[9];
    const float* bl1  = (const float*)d_in[10];
    const float* Wl2  = (const float*)d_in[11];
    const float* bl2  = (const float*)d_in[12];
    const float* Wa1  = (const float*)d_in[13];
    const float* ba1  = (const float*)d_in[14];
    const float* Wa2  = (const float*)d_in[15];
    const float* ba2  = (const float*)d_in[16];

    float *P, *eh, *et, *E1, *spill, *att, *red, *part, *tP;
    __nv_bfloat16 *Xbf, *h1b, *hb, *ehs, *ets, *Ub, *Vb;
    __nv_bfloat16 *Wfc1b, *Wfc2b, *Whdb, *Wtlb, *Wl1b, *Wl2b;
    int* tI;
    cudaGetSymbolAddress((void**)&P,     g_P);
    cudaGetSymbolAddress((void**)&eh,    g_eh);
    cudaGetSymbolAddress((void**)&et,    g_et);
    cudaGetSymbolAddress((void**)&E1,    g_E1);
    cudaGetSymbolAddress((void**)&spill, g_spill);
    cudaGetSymbolAddress((void**)&att,   g_att);
    cudaGetSymbolAddress((void**)&red,   g_red);
    cudaGetSymbolAddress((void**)&part,  g_part);
    cudaGetSymbolAddress((void**)&tI,    g_tI);
    cudaGetSymbolAddress((void**)&tP,    g_tP);
    cudaGetSymbolAddress((void**)&Xbf,   g_Xbf);
    cudaGetSymbolAddress((void**)&h1b,   g_h1b);
    cudaGetSymbolAddress((void**)&hb,    g_hb);
    cudaGetSymbolAddress((void**)&ehs,   g_ehs);
    cudaGetSymbolAddress((void**)&ets,   g_ets);
    cudaGetSymbolAddress((void**)&Ub,    g_Ub);
    cudaGetSymbolAddress((void**)&Vb,    g_Vb);
    cudaGetSymbolAddress((void**)&Wfc1b, g_Wfc1b);
    cudaGetSymbolAddress((void**)&Wfc2b, g_Wfc2b);
    cudaGetSymbolAddress((void**)&Whdb,  g_Whdb);
    cudaGetSymbolAddress((void**)&Wtlb,  g_Wtlb);
    cudaGetSymbolAddress((void**)&Wl1b,  g_Wl1b);
    cudaGetSymbolAddress((void**)&Wl2b,  g_Wl2b);

    cudaFuncSetAttribute(attn_mma_kernel,
                         cudaFuncAttributeMaxDynamicSharedMemorySize, 2 * MMA_STG);
    cudaFuncSetAttribute(mma_gemm_kernel<1, true,  false>,
                         cudaFuncAttributeMaxDynamicSharedMemorySize, 2 * MMA_STG);
    cudaFuncSetAttribute(mma_gemm_kernel<2, false, false>,
                         cudaFuncAttributeMaxDynamicSharedMemorySize, 2 * MMA_STG);
    cudaFuncSetAttribute(mma_gemm_kernel<3, false, false>,
                         cudaFuncAttributeMaxDynamicSharedMemorySize, 2 * MMA_STG);
    cudaFuncSetAttribute(mma_gemm_kernel<0, true,  false>,
                         cudaFuncAttributeMaxDynamicSharedMemorySize, 2 * MMA_STG);
    cudaFuncSetAttribute(mma_gemm_kernel<0, true,  true>,
                         cudaFuncAttributeMaxDynamicSharedMemorySize, 2 * MMA_STG);

    float* out = (float*)d_out;
    const size_t ND = (size_t)NN_ * DD_;
    float* e_out;
    float* eg_out;
    if ((size_t)out_size >= ND + DD_)      { e_out = out;   eg_out = out + ND; }
    else if ((size_t)out_size >= ND)       { e_out = out;   eg_out = nullptr;  }
    else                                   { e_out = spill; eg_out = out;      }

    const dim3 gG(2, 64);        // trunk GEMMs: N=256, M=8192
    const dim3 gA(64, 64);       // attn GEMM

    // prep: input + weight splits
    xsplit_kernel<<<NN_, 256>>>(x, Xbf);
    wprep_kernel<<<DIN_, 256>>>(Wfc1, Wfc1b, DIN_);
    wprep_kernel<<<DD_,  256>>>(Wfc2, Wfc2b, DD_);
    wprep_kernel<<<DD_,  256>>>(Whd,  Whdb,  DD_);
    wprep_kernel<<<DD_,  256>>>(Wtl,  Wtlb,  DD_);
    wprep_kernel<<<DD_,  256>>>(Wl1,  Wl1b,  DD_);
    wprep_kernel<<<DD_,  256>>>(Wl2,  Wl2b,  DD_);

    // trunk on tensor cores (4-term split, fp32-accurate)
    mma_gemm_kernel<1, true,  false><<<gG, 256, 2*MMA_STG>>>(Xbf, Wfc1b, bfc1, nullptr, nullptr, h1b, KAX_, 0.f);
    mma_gemm_kernel<1, true,  false><<<gG, 256, 2*MMA_STG>>>(h1b, Wfc2b, bfc2, nullptr, nullptr, hb,  KA4_, 0.f);
    mma_gemm_kernel<2, false, false><<<gG, 256, 2*MMA_STG>>>(hb,  Whdb,  bhd,  nullptr, eh,      ehs, KA4_, 0.0625f);
    mma_gemm_kernel<3, false, false><<<gG, 256, 2*MMA_STG>>>(hb,  Wtlb,  btl,  nullptr, et,      ets, KA4_, 0.f);

    // pairwise logits (3-term split) + top-k + neighbor aggregation
    attn_mma_kernel<<<gA, 256, 2*MMA_STG>>>(ehs, ets, P);
    topk_kernel    <<<NN_, 256>>>(P, tI, tP);
    neighbor_kernel<<<NN_, 256>>>(eh, et, tI, tP, Ub, Vb);

    // e = relu(U@Wl1+b) + relu(V@Wl2+b)
    mma_gemm_kernel<0, true, false><<<gG, 256, 2*MMA_STG>>>(Ub, Wl1b, bl1, nullptr, E1,    nullptr, KA4_, 0.f);
    mma_gemm_kernel<0, true, true ><<<gG, 256, 2*MMA_STG>>>(Vb, Wl2b, bl2, E1,      e_out, nullptr, KA4_, 0.f);

    if (eg_out) {
        att_kernel   <<<NN_ / 16, 128>>>(e_out, Wa1, ba1, Wa2, ba2, att);
        smred_kernel <<<1, 1024>>>(att, red);
        egpart_kernel<<<32, 256>>>(att, e_out, red, part);
        egfin_kernel <<<1, 256>>>(part, red, eg_out);
    }
}